// round 3
// baseline (speedup 1.0000x reference)
#include <cuda_runtime.h>

// ArtistBERT fused kernel, f32x2-packed GEMMs, fused QKV projection.
// One CTA per batch element, 128 threads (thread = hidden column).
// Residual stream / q / k stored TRANSPOSED in SMEM: [hidden d][seq s],
// row stride 20 floats (80B, 16B-aligned) so 16 seq positions load as 4x
// LDS.128 feeding fma.rn.f32x2 packed FMAs. V rides in registers across the
// scores/softmax phase and lands in the q buffer afterwards.

constexpr int S_ = 17;
constexpr int V_ = 29;
constexpr int D_ = 128;
constexpr int NSEG_ = 4;
constexpr int L_ = 6;
constexpr float EPS_ = 1e-5f;
constexpr int S_P = 20;  // transposed row stride (floats); 80B, 16B-aligned

typedef unsigned long long u64;

__device__ __forceinline__ u64 pack2(float x, float y) {
  u64 r;
  asm("mov.b64 %0, {%1, %2};" : "=l"(r) : "f"(x), "f"(y));
  return r;
}
__device__ __forceinline__ void unpack2(u64 v, float& x, float& y) {
  asm("mov.b64 {%0, %1}, %2;" : "=f"(x), "=f"(y) : "l"(v));
}
#define FFMA2(d, a, b) \
  asm("fma.rn.f32x2 %0, %1, %2, %0;" : "+l"(d) : "l"(a), "l"(b))

// Natural-order mapping: a2[j] accumulates seq pair {2j, 2j+1}; a16 = s16.
__device__ __forceinline__ void acc_init(u64* a2, float& a16, float bias) {
  u64 b2 = pack2(bias, bias);
#pragma unroll
  for (int i = 0; i < 8; i++) a2[i] = b2;
  a16 = bias;
}
__device__ __forceinline__ void acc_step(u64* a2, float& a16, u64 wp, float w,
                                         ulonglong2 r0, ulonglong2 r1,
                                         ulonglong2 r2, ulonglong2 r3,
                                         float x16) {
  FFMA2(a2[0], r0.x, wp);
  FFMA2(a2[1], r0.y, wp);
  FFMA2(a2[2], r1.x, wp);
  FFMA2(a2[3], r1.y, wp);
  FFMA2(a2[4], r2.x, wp);
  FFMA2(a2[5], r2.y, wp);
  FFMA2(a2[6], r3.x, wp);
  FFMA2(a2[7], r3.y, wp);
  a16 = fmaf(x16, w, a16);
}
__device__ __forceinline__ void acc_out(const u64* a2, float a16, float* v) {
#pragma unroll
  for (int j = 0; j < 8; j++) unpack2(a2[j], v[2 * j], v[2 * j + 1]);
  v[16] = a16;
}

// Single GEMM: acc[s] = bias + sum_k src_t[k][s] * W[k*D + c]
__device__ __forceinline__ void gemm17t(const float* __restrict__ src_t,
                                        const float* __restrict__ W,
                                        float bias, float* outv, int c) {
  u64 a2[8];
  float a16;
  acc_init(a2, a16, bias);
#pragma unroll 4
  for (int k = 0; k < D_; k++) {
    float w = W[k * D_ + c];
    u64 wp = pack2(w, w);
    const ulonglong2* row = reinterpret_cast<const ulonglong2*>(src_t + k * S_P);
    ulonglong2 r0 = row[0], r1 = row[1], r2 = row[2], r3 = row[3];
    acc_step(a2, a16, wp, w, r0, r1, r2, r3, src_t[k * S_P + 16]);
  }
  acc_out(a2, a16, outv);
}

__global__ void __launch_bounds__(128) artistbert_kernel(
    const float* __restrict__ X, const float* __restrict__ mask_in,
    const float* __restrict__ seg_in,
    const float* __restrict__ We, const float* __restrict__ be,
    const float* __restrict__ Wp, const float* __restrict__ bp,
    const float* __restrict__ Wsg, const float* __restrict__ bsg,
    const float* __restrict__ g1, const float* __restrict__ b1,
    const float* __restrict__ Wq, const float* __restrict__ bq,
    const float* __restrict__ Wk, const float* __restrict__ bk,
    const float* __restrict__ Wv, const float* __restrict__ bv,
    const float* __restrict__ g2, const float* __restrict__ b2,
    const float* __restrict__ Wd, const float* __restrict__ bd,
    const float* __restrict__ Wo, const float* __restrict__ bo,
    float* __restrict__ out)
{
  __shared__ __align__(16) float xs_t[D_ * S_P];  // residual stream [d][s]
  __shared__ __align__(16) float qs_t[D_ * S_P];  // q, later v      [d][s]
  __shared__ __align__(16) float ks_t[D_ * S_P];  // k               [d][s]
  __shared__ float sc[S_][S_ + 1];
  __shared__ float Xin[S_][V_ + 3];
  __shared__ float segw[S_][NSEG_];
  __shared__ float maskv[S_];
  __shared__ float mu_s[S_];
  __shared__ float rs_s[S_];

  const int b = blockIdx.x;
  const int c = threadIdx.x;  // hidden column 0..127

  // ---- cooperative per-batch input loads ----
  {
    const float* Xb = X + (long)b * (S_ * V_);
    for (int i = c; i < S_ * V_; i += 128) Xin[i / V_][i % V_] = Xb[i];
    if (c < S_ * NSEG_) segw[c / NSEG_][c % NSEG_] = seg_in[(long)b * (S_ * NSEG_) + c];
    if (c < S_) maskv[c] = mask_in[(long)b * S_ + c];
  }
  __syncthreads();

  float vals[S_];
  float vv[S_];  // v projection result, register-resident across scores phase

  // ---- embedding: X@We + be + (Wp+bp) + seg@Wsg + bsg ----
  {
    float acc[S_];
    float base = be[c] + bp[c] + bsg[c];
#pragma unroll
    for (int s = 0; s < S_; s++) {
      float a = base + Wp[s * D_ + c];
#pragma unroll
      for (int g = 0; g < NSEG_; g++) a = fmaf(segw[s][g], Wsg[g * D_ + c], a);
      acc[s] = a;
    }
#pragma unroll 4
    for (int v = 0; v < V_; v++) {
      float w = We[v * D_ + c];
#pragma unroll
      for (int s = 0; s < S_; s++) acc[s] = fmaf(Xin[s][v], w, acc[s]);
    }
#pragma unroll
    for (int s = 0; s < S_; s++) xs_t[c * S_P + s] = acc[s];
  }
  __syncthreads();

  for (int l = 0; l < L_; l++) {
    const float* Wql = Wq + (long)l * D_ * D_;
    const float* Wkl = Wk + (long)l * D_ * D_;
    const float* Wvl = Wv + (long)l * D_ * D_;
    const float* Wdl = Wd + (long)l * D_ * D_;

    // ---- fused q/k/v projections: share x-row loads across 3 accumulator sets ----
    {
      u64 aq[8], ak[8], av[8];
      float aq16, ak16, av16;
      acc_init(aq, aq16, bq[l * D_ + c]);
      acc_init(ak, ak16, bk[l * D_ + c]);
      acc_init(av, av16, bv[l * D_ + c]);
#pragma unroll 2
      for (int k = 0; k < D_; k++) {
        float wq = Wql[k * D_ + c];
        float wk = Wkl[k * D_ + c];
        float wv = Wvl[k * D_ + c];
        u64 wqp = pack2(wq, wq), wkp = pack2(wk, wk), wvp = pack2(wv, wv);
        const ulonglong2* row = reinterpret_cast<const ulonglong2*>(xs_t + k * S_P);
        ulonglong2 r0 = row[0], r1 = row[1], r2 = row[2], r3 = row[3];
        float x16 = xs_t[k * S_P + 16];
        acc_step(aq, aq16, wqp, wq, r0, r1, r2, r3, x16);
        acc_step(ak, ak16, wkp, wk, r0, r1, r2, r3, x16);
        acc_step(av, av16, wvp, wv, r0, r1, r2, r3, x16);
      }
      acc_out(aq, aq16, vals);
#pragma unroll
      for (int s = 0; s < S_; s++) qs_t[c * S_P + s] = fmaxf(vals[s], 0.f);
      acc_out(ak, ak16, vals);
#pragma unroll
      for (int s = 0; s < S_; s++) ks_t[c * S_P + s] = fmaxf(vals[s], 0.f);
      acc_out(av, av16, vv);
#pragma unroll
      for (int s = 0; s < S_; s++) vv[s] = fmaxf(vv[s], 0.f);  // v stays in regs
    }
    __syncthreads();

    // ---- scores = q @ k^T (289 dots over 128 threads) ----
    for (int e = c; e < S_ * S_; e += 128) {
      int qi = e / S_, ki = e % S_;
      float a = 0.f;
#pragma unroll 4
      for (int d = 0; d < D_; d++)
        a = fmaf(qs_t[d * S_P + qi], ks_t[d * S_P + ki], a);
      sc[qi][ki] = a;
    }
    __syncthreads();  // scores done; q buffer now dead

    // ---- softmax rows (threads<17); all threads park v into q buffer ----
    if (c < S_) {
      float m = sc[c][0];
#pragma unroll
      for (int k = 1; k < S_; k++) m = fmaxf(m, sc[c][k]);
      float sum = 0.f;
#pragma unroll
      for (int k = 0; k < S_; k++) { float p = __expf(sc[c][k] - m); sc[c][k] = p; sum += p; }
      float inv = __frcp_rn(sum);
#pragma unroll
      for (int k = 0; k < S_; k++) sc[c][k] *= inv;
    }
#pragma unroll
    for (int s = 0; s < S_; s++) qs_t[c * S_P + s] = vv[s];  // qs_t now holds v
    __syncthreads();

    // ---- attn = softmax @ v, mask, residual ----
    {
      float accA[S_];
#pragma unroll
      for (int s = 0; s < S_; s++) accA[s] = 0.f;
#pragma unroll
      for (int k = 0; k < S_; k++) {
        float vk = qs_t[c * S_P + k];
#pragma unroll
        for (int s = 0; s < S_; s++) accA[s] = fmaf(sc[s][k], vk, accA[s]);
      }
#pragma unroll
      for (int s = 0; s < S_; s++)
        xs_t[c * S_P + s] += accA[s] * maskv[s];
    }
    __syncthreads();

    // ---- LN1 ----
    if (c < S_) {
      float s1 = 0.f;
      for (int d = 0; d < D_; d++) s1 += xs_t[d * S_P + c];
      float m = s1 * (1.f / D_);
      float s2 = 0.f;
      for (int d = 0; d < D_; d++) { float t = xs_t[d * S_P + c] - m; s2 = fmaf(t, t, s2); }
      mu_s[c] = m;
      rs_s[c] = rsqrtf(s2 * (1.f / D_) + EPS_);
    }
    __syncthreads();
    {
      float g = g1[l * D_ + c], bb = b1[l * D_ + c];
#pragma unroll
      for (int s = 0; s < S_; s++)
        xs_t[c * S_P + s] = (xs_t[c * S_P + s] - mu_s[s]) * rs_s[s] * g + bb;
    }
    __syncthreads();

    // ---- FFN dense + residual ----
    gemm17t(xs_t, Wdl, bd[l * D_ + c], vals, c);
    __syncthreads();  // all gemm reads of xs_t complete before overwrite
#pragma unroll
    for (int s = 0; s < S_; s++) xs_t[c * S_P + s] += vals[s];
    __syncthreads();

    // ---- LN2 ----
    if (c < S_) {
      float s1 = 0.f;
      for (int d = 0; d < D_; d++) s1 += xs_t[d * S_P + c];
      float m = s1 * (1.f / D_);
      float s2 = 0.f;
      for (int d = 0; d < D_; d++) { float t = xs_t[d * S_P + c] - m; s2 = fmaf(t, t, s2); }
      mu_s[c] = m;
      rs_s[c] = rsqrtf(s2 * (1.f / D_) + EPS_);
    }
    __syncthreads();
    {
      float g = g2[l * D_ + c], bb = b2[l * D_ + c];
#pragma unroll
      for (int s = 0; s < S_; s++)
        xs_t[c * S_P + s] = (xs_t[c * S_P + s] - mu_s[s]) * rs_s[s] * g + bb;
    }
    __syncthreads();
  }

  // ---- output projection: x @ Wo + bo ----
  {
    float* ob = out + (long)b * (S_ * V_);
    for (int e = c; e < S_ * V_; e += 128) {
      int s = e / V_, vo = e % V_;
      float a = bo[vo];
#pragma unroll 4
      for (int d = 0; d < D_; d++)
        a = fmaf(xs_t[d * S_P + s], Wo[d * V_ + vo], a);
      ob[e] = a;
    }
  }
}

extern "C" void kernel_launch(void* const* d_in, const int* in_sizes, int n_in,
                              void* d_out, int out_size) {
  const float* X       = (const float*)d_in[0];
  const float* mask_in = (const float*)d_in[1];
  const float* seg_in  = (const float*)d_in[2];
  const float* We      = (const float*)d_in[3];
  const float* be      = (const float*)d_in[4];
  const float* Wp      = (const float*)d_in[5];
  const float* bp      = (const float*)d_in[6];
  const float* Wsg     = (const float*)d_in[7];
  const float* bsg     = (const float*)d_in[8];
  const float* g1      = (const float*)d_in[9];
  const float* b1      = (const float*)d_in[10];
  const float* Wq      = (const float*)d_in[11];
  const float* bq      = (const float*)d_in[12];
  const float* Wk      = (const float*)d_in[13];
  const float* bk      = (const float*)d_in[14];
  const float* Wv      = (const float*)d_in[15];
  const float* bv      = (const float*)d_in[16];
  const float* g2      = (const float*)d_in[17];
  const float* b2      = (const float*)d_in[18];
  const float* Wd      = (const float*)d_in[19];
  const float* bd      = (const float*)d_in[20];
  const float* Wo      = (const float*)d_in[21];
  const float* bo      = (const float*)d_in[22];
  float* out = (float*)d_out;

  int B = in_sizes[0] / (S_ * V_);
  artistbert_kernel<<<B, 128>>>(X, mask_in, seg_in, We, be, Wp, bp, Wsg, bsg,
                                g1, b1, Wq, bq, Wk, bk, Wv, bv, g2, b2, Wd, bd,
                                Wo, bo, out);
}

// round 4
// speedup vs baseline: 1.0923x; 1.0923x over previous
#include <cuda_runtime.h>

// ArtistBERT fused kernel, round 4.
// One CTA per batch element, 128 threads (thread = hidden column).
// Residual stream xs_t in [d][s] layout (stride 20) -> LDS.128 broadcast rows
// feed fma.rn.f32x2 in the big GEMMs (QKV fused, dense).
// q/k/v stored ROW-major [s][d] (stride 132) -> scores dot over contiguous d
// via LDS.128 + FFMA2. Scores stored transposed sc_t[k][q] (stride 20) so the
// attn phase does f32x2 over query pairs from broadcast LDS.128 rows, and
// softmax lanes read consecutive addresses (conflict-free).

constexpr int S_ = 17;
constexpr int V_ = 29;
constexpr int D_ = 128;
constexpr int NSEG_ = 4;
constexpr int L_ = 6;
constexpr float EPS_ = 1e-5f;
constexpr int S_P = 20;    // [d][s] row stride (floats); 80B, 16B-aligned
constexpr int DPAD = 132;  // [s][d] row stride (floats); 528B, 16B-aligned

typedef unsigned long long u64;

__device__ __forceinline__ u64 pack2(float x, float y) {
  u64 r;
  asm("mov.b64 %0, {%1, %2};" : "=l"(r) : "f"(x), "f"(y));
  return r;
}
__device__ __forceinline__ void unpack2(u64 v, float& x, float& y) {
  asm("mov.b64 {%0, %1}, %2;" : "=f"(x), "=f"(y) : "l"(v));
}
#define FFMA2(d, a, b) \
  asm("fma.rn.f32x2 %0, %1, %2, %0;" : "+l"(d) : "l"(a), "l"(b))

// a2[j] accumulates seq pair {2j,2j+1}; a16 = s16.
__device__ __forceinline__ void acc_init(u64* a2, float& a16, float bias) {
  u64 b2 = pack2(bias, bias);
#pragma unroll
  for (int i = 0; i < 8; i++) a2[i] = b2;
  a16 = bias;
}
__device__ __forceinline__ void acc_step(u64* a2, float& a16, u64 wp, float w,
                                         ulonglong2 r0, ulonglong2 r1,
                                         ulonglong2 r2, ulonglong2 r3,
                                         float x16) {
  FFMA2(a2[0], r0.x, wp);
  FFMA2(a2[1], r0.y, wp);
  FFMA2(a2[2], r1.x, wp);
  FFMA2(a2[3], r1.y, wp);
  FFMA2(a2[4], r2.x, wp);
  FFMA2(a2[5], r2.y, wp);
  FFMA2(a2[6], r3.x, wp);
  FFMA2(a2[7], r3.y, wp);
  a16 = fmaf(x16, w, a16);
}
__device__ __forceinline__ void acc_out(const u64* a2, float a16, float* v) {
#pragma unroll
  for (int j = 0; j < 8; j++) unpack2(a2[j], v[2 * j], v[2 * j + 1]);
  v[16] = a16;
}

// acc[s] = bias + sum_k src_t[k][s] * W[k*D + c]   (src_t in [d][s] layout)
__device__ __forceinline__ void gemm17t(const float* __restrict__ src_t,
                                        const float* __restrict__ W,
                                        float bias, float* outv, int c) {
  u64 a2[8];
  float a16;
  acc_init(a2, a16, bias);
#pragma unroll 4
  for (int k = 0; k < D_; k++) {
    float w = W[k * D_ + c];
    u64 wp = pack2(w, w);
    const ulonglong2* row = reinterpret_cast<const ulonglong2*>(src_t + k * S_P);
    ulonglong2 r0 = row[0], r1 = row[1], r2 = row[2], r3 = row[3];
    acc_step(a2, a16, wp, w, r0, r1, r2, r3, src_t[k * S_P + 16]);
  }
  acc_out(a2, a16, outv);
}

__global__ void __launch_bounds__(128) artistbert_kernel(
    const float* __restrict__ X, const float* __restrict__ mask_in,
    const float* __restrict__ seg_in,
    const float* __restrict__ We, const float* __restrict__ be,
    const float* __restrict__ Wp, const float* __restrict__ bp,
    const float* __restrict__ Wsg, const float* __restrict__ bsg,
    const float* __restrict__ g1, const float* __restrict__ b1,
    const float* __restrict__ Wq, const float* __restrict__ bq,
    const float* __restrict__ Wk, const float* __restrict__ bk,
    const float* __restrict__ Wv, const float* __restrict__ bv,
    const float* __restrict__ g2, const float* __restrict__ b2,
    const float* __restrict__ Wd, const float* __restrict__ bd,
    const float* __restrict__ Wo, const float* __restrict__ bo,
    float* __restrict__ out)
{
  __shared__ __align__(16) float xs_t[D_ * S_P];    // residual [d][s]
  __shared__ __align__(16) float qs_r[S_ * DPAD];   // q row-major, later v
  __shared__ __align__(16) float ks_r[S_ * DPAD];   // k row-major
  __shared__ __align__(16) float sc_t[S_ * S_P];    // scores [k][q]
  __shared__ float Xin[S_][V_ + 3];
  __shared__ float segw[S_][NSEG_];
  __shared__ float maskv[S_];
  __shared__ float mu_s[S_];
  __shared__ float rs_s[S_];

  const int b = blockIdx.x;
  const int c = threadIdx.x;  // hidden column 0..127

  // ---- cooperative per-batch input loads ----
  {
    const float* Xb = X + (long)b * (S_ * V_);
    for (int i = c; i < S_ * V_; i += 128) Xin[i / V_][i % V_] = Xb[i];
    if (c < S_ * NSEG_) segw[c / NSEG_][c % NSEG_] = seg_in[(long)b * (S_ * NSEG_) + c];
    if (c < S_) maskv[c] = mask_in[(long)b * S_ + c];
  }
  __syncthreads();

  float vals[S_];
  float vv[S_];  // v projection, register-resident across scores phase

  // ---- embedding: X@We + be + (Wp+bp) + seg@Wsg + bsg ----
  {
    float acc[S_];
    float base = be[c] + bp[c] + bsg[c];
#pragma unroll
    for (int s = 0; s < S_; s++) {
      float a = base + Wp[s * D_ + c];
#pragma unroll
      for (int g = 0; g < NSEG_; g++) a = fmaf(segw[s][g], Wsg[g * D_ + c], a);
      acc[s] = a;
    }
#pragma unroll 4
    for (int v = 0; v < V_; v++) {
      float w = We[v * D_ + c];
#pragma unroll
      for (int s = 0; s < S_; s++) acc[s] = fmaf(Xin[s][v], w, acc[s]);
    }
#pragma unroll
    for (int s = 0; s < S_; s++) xs_t[c * S_P + s] = acc[s];
  }
  __syncthreads();

  for (int l = 0; l < L_; l++) {
    const float* Wql = Wq + (long)l * D_ * D_;
    const float* Wkl = Wk + (long)l * D_ * D_;
    const float* Wvl = Wv + (long)l * D_ * D_;
    const float* Wdl = Wd + (long)l * D_ * D_;

    // ---- fused q/k/v projections (x-row loads shared by 3 accumulators) ----
    {
      u64 aq[8], ak[8], av[8];
      float aq16, ak16, av16;
      acc_init(aq, aq16, bq[l * D_ + c]);
      acc_init(ak, ak16, bk[l * D_ + c]);
      acc_init(av, av16, bv[l * D_ + c]);
#pragma unroll 2
      for (int k = 0; k < D_; k++) {
        float wq = Wql[k * D_ + c];
        float wk = Wkl[k * D_ + c];
        float wv = Wvl[k * D_ + c];
        u64 wqp = pack2(wq, wq), wkp = pack2(wk, wk), wvp = pack2(wv, wv);
        const ulonglong2* row = reinterpret_cast<const ulonglong2*>(xs_t + k * S_P);
        ulonglong2 r0 = row[0], r1 = row[1], r2 = row[2], r3 = row[3];
        float x16 = xs_t[k * S_P + 16];
        acc_step(aq, aq16, wqp, wq, r0, r1, r2, r3, x16);
        acc_step(ak, ak16, wkp, wk, r0, r1, r2, r3, x16);
        acc_step(av, av16, wvp, wv, r0, r1, r2, r3, x16);
      }
      // write q, k ROW-major (lanes consecutive -> conflict-free STS)
      acc_out(aq, aq16, vals);
#pragma unroll
      for (int s = 0; s < S_; s++) qs_r[s * DPAD + c] = fmaxf(vals[s], 0.f);
      acc_out(ak, ak16, vals);
#pragma unroll
      for (int s = 0; s < S_; s++) ks_r[s * DPAD + c] = fmaxf(vals[s], 0.f);
      acc_out(av, av16, vv);
#pragma unroll
      for (int s = 0; s < S_; s++) vv[s] = fmaxf(vv[s], 0.f);  // v stays in regs
    }
    __syncthreads();

    // ---- scores: dot over contiguous d via LDS.128 + FFMA2; store sc_t[k][q] ----
    for (int e = c; e < S_ * S_; e += 128) {
      int qi = e / S_, ki = e % S_;
      const ulonglong2* qrow = reinterpret_cast<const ulonglong2*>(qs_r + qi * DPAD);
      const ulonglong2* krow = reinterpret_cast<const ulonglong2*>(ks_r + ki * DPAD);
      u64 acc2 = pack2(0.f, 0.f);
#pragma unroll 4
      for (int d4 = 0; d4 < D_ / 4; d4++) {
        ulonglong2 qv = qrow[d4];
        ulonglong2 kv = krow[d4];
        FFMA2(acc2, qv.x, kv.x);
        FFMA2(acc2, qv.y, kv.y);
      }
      float ha, hb;
      unpack2(acc2, ha, hb);
      sc_t[ki * S_P + qi] = ha + hb;
    }
    __syncthreads();  // scores done; q buffer now dead

    // ---- softmax over k for each query row (threads<17, conflict-free lanes);
    //      all threads park v row-major into the dead q buffer ----
    if (c < S_) {
      float m = sc_t[0 * S_P + c];
#pragma unroll
      for (int k = 1; k < S_; k++) m = fmaxf(m, sc_t[k * S_P + c]);
      float sum = 0.f;
      float p[S_];
#pragma unroll
      for (int k = 0; k < S_; k++) { p[k] = __expf(sc_t[k * S_P + c] - m); sum += p[k]; }
      float inv = __frcp_rn(sum);
#pragma unroll
      for (int k = 0; k < S_; k++) sc_t[k * S_P + c] = p[k] * inv;
    }
#pragma unroll
    for (int s = 0; s < S_; s++) qs_r[s * DPAD + c] = vv[s];  // qs_r now holds v
    __syncthreads();

    // ---- attn = softmax @ v (f32x2 over query pairs), mask, residual ----
    {
      u64 aA[8];
      float aA16;
      acc_init(aA, aA16, 0.f);
#pragma unroll
      for (int k = 0; k < S_; k++) {
        float vk = qs_r[k * DPAD + c];  // lanes consecutive -> conflict-free
        u64 vkp = pack2(vk, vk);
        const ulonglong2* srow = reinterpret_cast<const ulonglong2*>(sc_t + k * S_P);
        ulonglong2 r0 = srow[0], r1 = srow[1], r2 = srow[2], r3 = srow[3];
        acc_step(aA, aA16, vkp, vk, r0, r1, r2, r3, sc_t[k * S_P + 16]);
      }
      acc_out(aA, aA16, vals);
#pragma unroll
      for (int s = 0; s < S_; s++)
        xs_t[c * S_P + s] += vals[s] * maskv[s];
    }
    __syncthreads();

    // ---- LN1 ----
    if (c < S_) {
      float s1 = 0.f;
      for (int d = 0; d < D_; d++) s1 += xs_t[d * S_P + c];
      float m = s1 * (1.f / D_);
      float s2 = 0.f;
      for (int d = 0; d < D_; d++) { float t = xs_t[d * S_P + c] - m; s2 = fmaf(t, t, s2); }
      mu_s[c] = m;
      rs_s[c] = rsqrtf(s2 * (1.f / D_) + EPS_);
    }
    __syncthreads();
    {
      float g = g1[l * D_ + c], bb = b1[l * D_ + c];
#pragma unroll
      for (int s = 0; s < S_; s++)
        xs_t[c * S_P + s] = (xs_t[c * S_P + s] - mu_s[s]) * rs_s[s] * g + bb;
    }
    __syncthreads();

    // ---- FFN dense + residual ----
    gemm17t(xs_t, Wdl, bd[l * D_ + c], vals, c);
    __syncthreads();  // all gemm reads of xs_t complete before overwrite
#pragma unroll
    for (int s = 0; s < S_; s++) xs_t[c * S_P + s] += vals[s];
    __syncthreads();

    // ---- LN2 ----
    if (c < S_) {
      float s1 = 0.f;
      for (int d = 0; d < D_; d++) s1 += xs_t[d * S_P + c];
      float m = s1 * (1.f / D_);
      float s2 = 0.f;
      for (int d = 0; d < D_; d++) { float t = xs_t[d * S_P + c] - m; s2 = fmaf(t, t, s2); }
      mu_s[c] = m;
      rs_s[c] = rsqrtf(s2 * (1.f / D_) + EPS_);
    }
    __syncthreads();
    {
      float g = g2[l * D_ + c], bb = b2[l * D_ + c];
#pragma unroll
      for (int s = 0; s < S_; s++)
        xs_t[c * S_P + s] = (xs_t[c * S_P + s] - mu_s[s]) * rs_s[s] * g + bb;
    }
    __syncthreads();
  }

  // ---- output projection: x @ Wo + bo ----
  {
    float* ob = out + (long)b * (S_ * V_);
    for (int e = c; e < S_ * V_; e += 128) {
      int s = e / V_, vo = e % V_;
      float a = bo[vo];
#pragma unroll 4
      for (int d = 0; d < D_; d++)
        a = fmaf(xs_t[d * S_P + s], Wo[d * V_ + vo], a);
      ob[e] = a;
    }
  }
}

extern "C" void kernel_launch(void* const* d_in, const int* in_sizes, int n_in,
                              void* d_out, int out_size) {
  const float* X       = (const float*)d_in[0];
  const float* mask_in = (const float*)d_in[1];
  const float* seg_in  = (const float*)d_in[2];
  const float* We      = (const float*)d_in[3];
  const float* be      = (const float*)d_in[4];
  const float* Wp      = (const float*)d_in[5];
  const float* bp      = (const float*)d_in[6];
  const float* Wsg     = (const float*)d_in[7];
  const float* bsg     = (const float*)d_in[8];
  const float* g1      = (const float*)d_in[9];
  const float* b1      = (const float*)d_in[10];
  const float* Wq      = (const float*)d_in[11];
  const float* bq      = (const float*)d_in[12];
  const float* Wk      = (const float*)d_in[13];
  const float* bk      = (const float*)d_in[14];
  const float* Wv      = (const float*)d_in[15];
  const float* bv      = (const float*)d_in[16];
  const float* g2      = (const float*)d_in[17];
  const float* b2      = (const float*)d_in[18];
  const float* Wd      = (const float*)d_in[19];
  const float* bd      = (const float*)d_in[20];
  const float* Wo      = (const float*)d_in[21];
  const float* bo      = (const float*)d_in[22];
  float* out = (float*)d_out;

  int B = in_sizes[0] / (S_ * V_);
  artistbert_kernel<<<B, 128>>>(X, mask_in, seg_in, We, be, Wp, bp, Wsg, bsg,
                                g1, b1, Wq, bq, Wk, bk, Wv, bv, g2, b2, Wd, bd,
                                Wo, bo, out);
}

// round 16
// speedup vs baseline: 1.1002x; 1.0072x over previous
#include <cuda_runtime.h>

// ArtistBERT fused kernel, rounds 9-15 (unchanged; awaiting first measurement).
// One CTA per batch element, 128 threads (thread = hidden column), 6 CTAs/SM.
// Residual xs_t in [d][s] layout (stride 20): LDS.128 broadcast rows feed
// fma.rn.f32x2 in the QKV-fused and dense GEMMs. q/k row-major [s][d];
// scores transposed sc_t[k][q]. Parallel all-warp LN stats. V register-
// resident. Per-thread passes over xs_t's own row (embedding store, attn
// residual, LN scales, dense residual) use float4 LDS.128/STS.128 — the
// scalar versions were 4-way bank conflicted (stride 80B, gcd(20,32)=4).

constexpr int S_ = 17;
constexpr int V_ = 29;
constexpr int D_ = 128;
constexpr int NSEG_ = 4;
constexpr int L_ = 6;
constexpr float EPS_ = 1e-5f;
constexpr int S_P = 20;    // [d][s] row stride (floats); 80B, 16B-aligned
constexpr int DPAD = 132;  // [s][d] row stride (floats); 528B, 16B-aligned

typedef unsigned long long u64;

__device__ __forceinline__ u64 pack2(float x, float y) {
  u64 r;
  asm("mov.b64 %0, {%1, %2};" : "=l"(r) : "f"(x), "f"(y));
  return r;
}
__device__ __forceinline__ void unpack2(u64 v, float& x, float& y) {
  asm("mov.b64 {%0, %1}, %2;" : "=f"(x), "=f"(y) : "l"(v));
}
#define FFMA2(d, a, b) \
  asm("fma.rn.f32x2 %0, %1, %2, %0;" : "+l"(d) : "l"(a), "l"(b))

// a2[j] accumulates seq pair {2j,2j+1}; a16 = s16.
__device__ __forceinline__ void acc_init(u64* a2, float& a16, float bias) {
  u64 b2 = pack2(bias, bias);
#pragma unroll
  for (int i = 0; i < 8; i++) a2[i] = b2;
  a16 = bias;
}
__device__ __forceinline__ void acc_step(u64* a2, float& a16, u64 wp, float w,
                                         ulonglong2 r0, ulonglong2 r1,
                                         ulonglong2 r2, ulonglong2 r3,
                                         float x16) {
  FFMA2(a2[0], r0.x, wp);
  FFMA2(a2[1], r0.y, wp);
  FFMA2(a2[2], r1.x, wp);
  FFMA2(a2[3], r1.y, wp);
  FFMA2(a2[4], r2.x, wp);
  FFMA2(a2[5], r2.y, wp);
  FFMA2(a2[6], r3.x, wp);
  FFMA2(a2[7], r3.y, wp);
  a16 = fmaf(x16, w, a16);
}
__device__ __forceinline__ void acc_out(const u64* a2, float a16, float* v) {
#pragma unroll
  for (int j = 0; j < 8; j++) unpack2(a2[j], v[2 * j], v[2 * j + 1]);
  v[16] = a16;
}

// acc[s] = bias + sum_k src_t[k][s] * W[k*D + c]   (src_t in [d][s] layout)
__device__ __forceinline__ void gemm17t(const float* __restrict__ src_t,
                                        const float* __restrict__ W,
                                        float bias, float* outv, int c) {
  u64 a2[8];
  float a16;
  acc_init(a2, a16, bias);
#pragma unroll 4
  for (int k = 0; k < D_; k++) {
    float w = W[k * D_ + c];
    u64 wp = pack2(w, w);
    const ulonglong2* row = reinterpret_cast<const ulonglong2*>(src_t + k * S_P);
    ulonglong2 r0 = row[0], r1 = row[1], r2 = row[2], r3 = row[3];
    acc_step(a2, a16, wp, w, r0, r1, r2, r3, src_t[k * S_P + 16]);
  }
  acc_out(a2, a16, outv);
}

// Parallel LN stats: all 4 warps; warp `wid` handles rows s = wid, wid+4, ...
// Lane j sums columns d = j, j+32, j+64, j+96; butterfly combines.
__device__ __forceinline__ void ln_stats(const float* __restrict__ xs_t,
                                         float* __restrict__ mu_s,
                                         float* __restrict__ rs_s,
                                         int wid, int lane) {
  for (int s = wid; s < S_; s += 4) {
    float x0 = xs_t[lane * S_P + s];
    float x1 = xs_t[(lane + 32) * S_P + s];
    float x2 = xs_t[(lane + 64) * S_P + s];
    float x3 = xs_t[(lane + 96) * S_P + s];
    float sum = (x0 + x1) + (x2 + x3);
    float sq = fmaf(x0, x0, fmaf(x1, x1, fmaf(x2, x2, x3 * x3)));
#pragma unroll
    for (int off = 16; off >= 1; off >>= 1) {
      sum += __shfl_xor_sync(0xffffffffu, sum, off);
      sq += __shfl_xor_sync(0xffffffffu, sq, off);
    }
    if (lane == 0) {
      float m = sum * (1.f / D_);
      float var = fmaxf(sq * (1.f / D_) - m * m, 0.f);
      mu_s[s] = m;
      rs_s[s] = rsqrtf(var + EPS_);
    }
  }
}

// y = (x - mu)*rs*g + bb over this thread's contiguous row, vectorized.
__device__ __forceinline__ void ln_scale_row(float* __restrict__ rowp,
                                             const float* __restrict__ mu_s,
                                             const float* __restrict__ rs_s,
                                             float g, float bb) {
  float4* row4 = reinterpret_cast<float4*>(rowp);
#pragma unroll
  for (int j = 0; j < 4; j++) {
    float4 x = row4[j];
    x.x = (x.x - mu_s[4 * j + 0]) * rs_s[4 * j + 0] * g + bb;
    x.y = (x.y - mu_s[4 * j + 1]) * rs_s[4 * j + 1] * g + bb;
    x.z = (x.z - mu_s[4 * j + 2]) * rs_s[4 * j + 2] * g + bb;
    x.w = (x.w - mu_s[4 * j + 3]) * rs_s[4 * j + 3] * g + bb;
    row4[j] = x;
  }
  rowp[16] = (rowp[16] - mu_s[16]) * rs_s[16] * g + bb;
}

__global__ void __launch_bounds__(128, 6) artistbert_kernel(
    const float* __restrict__ X, const float* __restrict__ mask_in,
    const float* __restrict__ seg_in,
    const float* __restrict__ We, const float* __restrict__ be,
    const float* __restrict__ Wp, const float* __restrict__ bp,
    const float* __restrict__ Wsg, const float* __restrict__ bsg,
    const float* __restrict__ g1, const float* __restrict__ b1,
    const float* __restrict__ Wq, const float* __restrict__ bq,
    const float* __restrict__ Wk, const float* __restrict__ bk,
    const float* __restrict__ Wv, const float* __restrict__ bv,
    const float* __restrict__ g2, const float* __restrict__ b2,
    const float* __restrict__ Wd, const float* __restrict__ bd,
    const float* __restrict__ Wo, const float* __restrict__ bo,
    float* __restrict__ out)
{
  __shared__ __align__(16) float xs_t[D_ * S_P];    // residual [d][s]
  __shared__ __align__(16) float qs_r[S_ * DPAD];   // q row-major
  __shared__ __align__(16) float ks_r[S_ * DPAD];   // k row-major
  __shared__ __align__(16) float sc_t[S_ * S_P];    // scores [k][q]
  __shared__ float Xin[S_][V_ + 3];
  __shared__ float segw[S_][NSEG_];
  __shared__ float maskv[S_];
  __shared__ float mu_s[S_];
  __shared__ float rs_s[S_];

  const int b = blockIdx.x;
  const int c = threadIdx.x;  // hidden column 0..127
  const int wid = c >> 5;
  const int lane = c & 31;
  float* myrow = xs_t + c * S_P;  // this thread's contiguous residual row

  // ---- cooperative per-batch input loads ----
  {
    const float* Xb = X + (long)b * (S_ * V_);
    for (int i = c; i < S_ * V_; i += 128) Xin[i / V_][i % V_] = Xb[i];
    if (c < S_ * NSEG_) segw[c / NSEG_][c % NSEG_] = seg_in[(long)b * (S_ * NSEG_) + c];
    if (c < S_) maskv[c] = mask_in[(long)b * S_ + c];
  }
  __syncthreads();

  float vals[S_];
  float vv[S_];  // v projection: thread c holds v[s][c], used directly in attn

  // ---- embedding: X@We + be + (Wp+bp) + seg@Wsg + bsg ----
  {
    float acc[S_];
    float base = be[c] + bp[c] + bsg[c];
#pragma unroll
    for (int s = 0; s < S_; s++) {
      float a = base + Wp[s * D_ + c];
#pragma unroll
      for (int g = 0; g < NSEG_; g++) a = fmaf(segw[s][g], Wsg[g * D_ + c], a);
      acc[s] = a;
    }
#pragma unroll 4
    for (int v = 0; v < V_; v++) {
      float w = We[v * D_ + c];
#pragma unroll
      for (int s = 0; s < S_; s++) acc[s] = fmaf(Xin[s][v], w, acc[s]);
    }
    float4* row4 = reinterpret_cast<float4*>(myrow);
#pragma unroll
    for (int j = 0; j < 4; j++)
      row4[j] = make_float4(acc[4 * j], acc[4 * j + 1], acc[4 * j + 2], acc[4 * j + 3]);
    myrow[16] = acc[16];
  }
  __syncthreads();

  for (int l = 0; l < L_; l++) {
    const float* Wql = Wq + (long)l * D_ * D_;
    const float* Wkl = Wk + (long)l * D_ * D_;
    const float* Wvl = Wv + (long)l * D_ * D_;
    const float* Wdl = Wd + (long)l * D_ * D_;

    // ---- fused q/k/v projections (x-row loads shared by 3 accumulators) ----
    {
      u64 aq[8], ak[8], av[8];
      float aq16, ak16, av16;
      acc_init(aq, aq16, bq[l * D_ + c]);
      acc_init(ak, ak16, bk[l * D_ + c]);
      acc_init(av, av16, bv[l * D_ + c]);
#pragma unroll 2
      for (int k = 0; k < D_; k++) {
        float wq = Wql[k * D_ + c];
        float wk = Wkl[k * D_ + c];
        float wv = Wvl[k * D_ + c];
        u64 wqp = pack2(wq, wq), wkp = pack2(wk, wk), wvp = pack2(wv, wv);
        const ulonglong2* row = reinterpret_cast<const ulonglong2*>(xs_t + k * S_P);
        ulonglong2 r0 = row[0], r1 = row[1], r2 = row[2], r3 = row[3];
        float x16 = xs_t[k * S_P + 16];
        acc_step(aq, aq16, wqp, wq, r0, r1, r2, r3, x16);
        acc_step(ak, ak16, wkp, wk, r0, r1, r2, r3, x16);
        acc_step(av, av16, wvp, wv, r0, r1, r2, r3, x16);
      }
      acc_out(aq, aq16, vals);
#pragma unroll
      for (int s = 0; s < S_; s++) qs_r[s * DPAD + c] = fmaxf(vals[s], 0.f);
      acc_out(ak, ak16, vals);
#pragma unroll
      for (int s = 0; s < S_; s++) ks_r[s * DPAD + c] = fmaxf(vals[s], 0.f);
      acc_out(av, av16, vv);
#pragma unroll
      for (int s = 0; s < S_; s++) vv[s] = fmaxf(vv[s], 0.f);  // v stays in regs
    }
    __syncthreads();

    // ---- scores: dot over contiguous d via LDS.128 + FFMA2; store sc_t[k][q] ----
    for (int e = c; e < S_ * S_; e += 128) {
      int qi = e / S_, ki = e % S_;
      const ulonglong2* qrow = reinterpret_cast<const ulonglong2*>(qs_r + qi * DPAD);
      const ulonglong2* krow = reinterpret_cast<const ulonglong2*>(ks_r + ki * DPAD);
      u64 acc2 = pack2(0.f, 0.f);
#pragma unroll 4
      for (int d4 = 0; d4 < D_ / 4; d4++) {
        ulonglong2 qv = qrow[d4];
        ulonglong2 kv = krow[d4];
        FFMA2(acc2, qv.x, kv.x);
        FFMA2(acc2, qv.y, kv.y);
      }
      float ha, hb;
      unpack2(acc2, ha, hb);
      sc_t[ki * S_P + qi] = ha + hb;
    }
    __syncthreads();

    // ---- softmax over k per query (threads<17, conflict-free lanes) ----
    if (c < S_) {
      float m = sc_t[0 * S_P + c];
#pragma unroll
      for (int k = 1; k < S_; k++) m = fmaxf(m, sc_t[k * S_P + c]);
      float sum = 0.f;
#pragma unroll
      for (int k = 0; k < S_; k++) {
        float p = __expf(sc_t[k * S_P + c] - m);
        sc_t[k * S_P + c] = p;
        sum += p;
      }
      float inv = __frcp_rn(sum);
#pragma unroll
      for (int k = 0; k < S_; k++) sc_t[k * S_P + c] *= inv;
    }
    __syncthreads();  // sc_t visible to all threads

    // ---- attn = softmax @ v: v from this thread's registers; residual f32x4 ----
    {
      u64 aA[8];
      float aA16;
      acc_init(aA, aA16, 0.f);
#pragma unroll
      for (int k = 0; k < S_; k++) {
        float vk = vv[k];  // v[k][c] — register-resident
        u64 vkp = pack2(vk, vk);
        const ulonglong2* srow = reinterpret_cast<const ulonglong2*>(sc_t + k * S_P);
        ulonglong2 r0 = srow[0], r1 = srow[1], r2 = srow[2], r3 = srow[3];
        acc_step(aA, aA16, vkp, vk, r0, r1, r2, r3, sc_t[k * S_P + 16]);
      }
      acc_out(aA, aA16, vals);
      float4* row4 = reinterpret_cast<float4*>(myrow);
#pragma unroll
      for (int j = 0; j < 4; j++) {
        float4 x = row4[j];
        x.x = fmaf(vals[4 * j + 0], maskv[4 * j + 0], x.x);
        x.y = fmaf(vals[4 * j + 1], maskv[4 * j + 1], x.y);
        x.z = fmaf(vals[4 * j + 2], maskv[4 * j + 2], x.z);
        x.w = fmaf(vals[4 * j + 3], maskv[4 * j + 3], x.w);
        row4[j] = x;
      }
      myrow[16] = fmaf(vals[16], maskv[16], myrow[16]);
    }
    __syncthreads();

    // ---- LN1: parallel stats, then vectorized scale ----
    ln_stats(xs_t, mu_s, rs_s, wid, lane);
    __syncthreads();
    ln_scale_row(myrow, mu_s, rs_s, g1[l * D_ + c], b1[l * D_ + c]);
    __syncthreads();

    // ---- FFN dense + residual (vectorized) ----
    gemm17t(xs_t, Wdl, bd[l * D_ + c], vals, c);
    __syncthreads();  // all gemm reads of xs_t complete before overwrite
    {
      float4* row4 = reinterpret_cast<float4*>(myrow);
#pragma unroll
      for (int j = 0; j < 4; j++) {
        float4 x = row4[j];
        x.x += vals[4 * j + 0];
        x.y += vals[4 * j + 1];
        x.z += vals[4 * j + 2];
        x.w += vals[4 * j + 3];
        row4[j] = x;
      }
      myrow[16] += vals[16];
    }
    __syncthreads();

    // ---- LN2: parallel stats, then vectorized scale ----
    ln_stats(xs_t, mu_s, rs_s, wid, lane);
    __syncthreads();
    ln_scale_row(myrow, mu_s, rs_s, g2[l * D_ + c], b2[l * D_ + c]);
    __syncthreads();
  }

  // ---- output projection: x @ Wo + bo ----
  {
    float* ob = out + (long)b * (S_ * V_);
    for (int e = c; e < S_ * V_; e += 128) {
      int s = e / V_, vo = e % V_;
      float a = bo[vo];
#pragma unroll 4
      for (int d = 0; d < D_; d++)
        a = fmaf(xs_t[d * S_P + s], Wo[d * V_ + vo], a);
      ob[e] = a;
    }
  }
}

extern "C" void kernel_launch(void* const* d_in, const int* in_sizes, int n_in,
                              void* d_out, int out_size) {
  const float* X       = (const float*)d_in[0];
  const float* mask_in = (const float*)d_in[1];
  const float* seg_in  = (const float*)d_in[2];
  const float* We      = (const float*)d_in[3];
  const float* be      = (const float*)d_in[4];
  const float* Wp      = (const float*)d_in[5];
  const float* bp      = (const float*)d_in[6];
  const float* Wsg     = (const float*)d_in[7];
  const float* bsg     = (const float*)d_in[8];
  const float* g1      = (const float*)d_in[9];
  const float* b1      = (const float*)d_in[10];
  const float* Wq      = (const float*)d_in[11];
  const float* bq      = (const float*)d_in[12];
  const float* Wk      = (const float*)d_in[13];
  const float* bk      = (const float*)d_in[14];
  const float* Wv      = (const float*)d_in[15];
  const float* bv      = (const float*)d_in[16];
  const float* g2      = (const float*)d_in[17];
  const float* b2      = (const float*)d_in[18];
  const float* Wd      = (const float*)d_in[19];
  const float* bd      = (const float*)d_in[20];
  const float* Wo      = (const float*)d_in[21];
  const float* bo      = (const float*)d_in[22];
  float* out = (float*)d_out;

  int B = in_sizes[0] / (S_ * V_);
  artistbert_kernel<<<B, 128>>>(X, mask_in, seg_in, We, be, Wp, bp, Wsg, bsg,
                                g1, b1, Wq, bq, Wk, bk, Wv, bv, g2, b2, Wd, bd,
                                Wo, bo, out);
}